// round 11
// baseline (speedup 1.0000x reference)
#include <cuda_runtime.h>
#include <math.h>

#define Bn    16
#define Hn    512
#define Wn    512
#define HWn   (Hn * Wn)

// tile: 64x16 outputs, halo 3 each side
#define TW    64
#define TH    16
#define EXTH  22          // TH + 6
#define SRS   72          // s_r cols: gc tx0-4 .. tx0+67
#define HSS   68          // h-sum stride

#define NBLK  4096        // 8 x 32 x 16 (image b owns slots [b*256, b*256+256))

__device__ float g_psum[NBLK], g_psq[NBLK], g_pS[NBLK];
__device__ unsigned int g_ctr;   // self-resetting last-block counter

__device__ __forceinline__ float warpRed(float v) {
    #pragma unroll
    for (int o = 16; o; o >>= 1) v += __shfl_down_sync(0xffffffffu, v, o);
    return v;
}
__device__ __forceinline__ double warpRedD(double v) {
    #pragma unroll
    for (int o = 16; o; o >>= 1) v += __shfl_down_sync(0xffffffffu, v, o);
    return v;
}
__device__ __forceinline__ int refl(int i) {
    i = (i < 0) ? -i : i;
    return (i >= Hn) ? (2 * (Hn - 1) - i) : i;
}

// ---------------------------------------------------------------------------
// ONE fused pass: residual + gate + per-image stats + separable 7x7 unbiased
// local variance (reflect pad) + gated loss partial + FENCE-FREE last-block
// combine (release-atomic counter + L1-bypass partial traffic; no CCTL.IVALL).
// ---------------------------------------------------------------------------
__global__ __launch_bounds__(256, 6) void k_fused(const float* __restrict__ outp,
                                                  const float* __restrict__ emap,
                                                  const float* __restrict__ gtp,
                                                  float* __restrict__ out) {
    __shared__ float  s_r [EXTH * SRS];   // rs (>=0) halo tile
    __shared__ float  s_hs[EXTH * HSS];   // horizontal 7-sum
    __shared__ float  s_hq[EXTH * HSS];   // horizontal 7-sum of squares
    __shared__ uchar4 s_g [256];          // gate bytes, 4 px each
    __shared__ float  sh  [24];
    __shared__ double shd [16];
    __shared__ bool   isLast;

    int b   = blockIdx.z;
    int tx0 = blockIdx.x * TW;
    int ty0 = blockIdx.y * TH;
    int tid = threadIdx.x;
    int A0  = tx0 - 4;

    size_t bbase = (size_t)b * 3 * HWn;
    const float* gb = gtp  + bbase;
    const float* ob = outp + bbase;
    const float* eb = emap + bbase;

    // Phase 1: rs over halo tile, float4, row-reflect always (free).
    for (int i = tid; i < EXTH * 18; i += 256) {
        int row = i / 18, f4 = i - row * 18;
        int cb  = A0 + f4 * 4;
        if (cb >= 0 && cb <= Wn - 4) {
            int base = refl(ty0 + row - 3) * Wn + cb;
            float4 g0 = *(const float4*)(gb + base);
            float4 g1 = *(const float4*)(gb + base + HWn);
            float4 g2 = *(const float4*)(gb + base + 2 * HWn);
            float4 o0 = *(const float4*)(ob + base);
            float4 o1 = *(const float4*)(ob + base + HWn);
            float4 o2 = *(const float4*)(ob + base + 2 * HWn);
            float4 rs;
            rs.x = fabsf(g0.x-o0.x)+fabsf(g1.x-o1.x)+fabsf(g2.x-o2.x);
            rs.y = fabsf(g0.y-o0.y)+fabsf(g1.y-o1.y)+fabsf(g2.y-o2.y);
            rs.z = fabsf(g0.z-o0.z)+fabsf(g1.z-o1.z)+fabsf(g2.z-o2.z);
            rs.w = fabsf(g0.w-o0.w)+fabsf(g1.w-o1.w)+fabsf(g2.w-o2.w);
            *(float4*)&s_r[row * SRS + f4 * 4] = rs;
        }
    }
    __syncthreads();

    // Column-edge mirror fixup (left: gc -4..-1 ; right: gc 512..515).
    if (blockIdx.x == 0) {
        for (int i = tid; i < EXTH * 4; i += 256) {
            int row = i >> 2, k = i & 3;
            s_r[row * SRS + k] = s_r[row * SRS + 8 - k];
        }
    } else if (blockIdx.x == (Wn / TW) - 1) {
        for (int i = tid; i < EXTH * 4; i += 256) {
            int row = i >> 2, k = i & 3;
            s_r[row * SRS + 68 + k] = s_r[row * SRS + 66 - k];
        }
    }

    // Gate + per-image stats on center pixels (gt/out L1-hot, ema fresh).
    float lsum, lsq;
    {
        int r  = tid >> 4;
        int c4 = (tid & 15) * 4;
        int base = (ty0 + r) * Wn + tx0 + c4;
        float4 g0 = *(const float4*)(gb + base);
        float4 g1 = *(const float4*)(gb + base + HWn);
        float4 g2 = *(const float4*)(gb + base + 2 * HWn);
        float4 e0 = *(const float4*)(eb + base);
        float4 e1 = *(const float4*)(eb + base + HWn);
        float4 e2 = *(const float4*)(eb + base + 2 * HWn);
        float4 rs = *(const float4*)&s_r[(r + 3) * SRS + c4 + 4];
        float4 re;
        re.x = fabsf(g0.x-e0.x)+fabsf(g1.x-e1.x)+fabsf(g2.x-e2.x);
        re.y = fabsf(g0.y-e0.y)+fabsf(g1.y-e1.y)+fabsf(g2.y-e2.y);
        re.z = fabsf(g0.z-e0.z)+fabsf(g1.z-e1.z)+fabsf(g2.z-e2.z);
        re.w = fabsf(g0.w-e0.w)+fabsf(g1.w-e1.w)+fabsf(g2.w-e2.w);
        uchar4 gv;
        gv.x = (rs.x < re.x) ? 0 : 1;
        gv.y = (rs.y < re.y) ? 0 : 1;
        gv.z = (rs.z < re.z) ? 0 : 1;
        gv.w = (rs.w < re.w) ? 0 : 1;
        s_g[tid] = gv;
        lsum = rs.x + rs.y + rs.z + rs.w;
        lsq  = rs.x*rs.x + rs.y*rs.y + rs.z*rs.z + rs.w*rs.w;
    }
    __syncthreads();

    // Phase 2: horizontal 7-taps, 4 outputs/thread, sliding window.
    for (int i = tid; i < EXTH * 16; i += 256) {
        int row = i >> 4;
        int g4  = (i & 15) << 2;
        const float* rp = &s_r[row * SRS + g4];
        float4 A  = *(const float4*)(rp);
        float4 Bv = *(const float4*)(rp + 4);
        float4 Cv = *(const float4*)(rp + 8);
        float v0=A.y, v1=A.z, v2=A.w, v3=Bv.x, v4=Bv.y, v5=Bv.z, v6=Bv.w;
        float v7=Cv.x, v8=Cv.y, v9=Cv.z;
        float s0 = v0+v1+v2+v3+v4+v5+v6;
        float s1 = s0 - v0 + v7;
        float s2 = s1 - v1 + v8;
        float s3 = s2 - v2 + v9;
        float q0 = v0*v0+v1*v1+v2*v2+v3*v3+v4*v4+v5*v5+v6*v6;
        float q1 = q0 + (v7*v7 - v0*v0);
        float q2 = q1 + (v8*v8 - v1*v1);
        float q3 = q2 + (v9*v9 - v2*v2);
        *(float4*)&s_hs[row * HSS + g4] = make_float4(s0, s1, s2, s3);
        *(float4*)&s_hq[row * HSS + g4] = make_float4(q0, q1, q2, q3);
    }
    __syncthreads();

    // Phase 3: vertical 7-taps, register sliding window, 4 rows/thread.
    int c  = tid & 63;
    int r0 = (tid >> 6) * 4;
    float s = 0.f, q = 0.f;
    #pragma unroll
    for (int d = 0; d < 7; d++) {
        s += s_hs[(r0 + d) * HSS + c];
        q += s_hq[(r0 + d) * HSS + c];
    }
    float acc = 0.f;
    #pragma unroll
    for (int k = 0; k < 4; k++) {
        int r = r0 + k;
        float var = (q - s * s * (1.f / 49.f)) * (1.f / 48.f);
        float rs  = s_r[(r + 3) * SRS + c + 4];
        uchar4 gv = s_g[r * 16 + (c >> 2)];
        unsigned char gbit = (c & 2) ? ((c & 1) ? gv.w : gv.z)
                                     : ((c & 1) ? gv.y : gv.x);
        if (gbit) acc += fabsf(var) * rs;
        if (k < 3) {
            s += s_hs[(r + 7) * HSS + c] - s_hs[r * HSS + c];
            q += s_hq[(r + 7) * HSS + c] - s_hq[r * HSS + c];
        }
    }

    // Block reduce (lsum, lsq, acc) -> per-block partials.
    float a0 = warpRed(lsum), a1 = warpRed(lsq), a2 = warpRed(acc);
    int lane = tid & 31, w = tid >> 5;
    if (lane == 0) { sh[w] = a0; sh[8 + w] = a1; sh[16 + w] = a2; }
    __syncthreads();
    int blk = (blockIdx.z * 32 + blockIdx.y) * 8 + blockIdx.x;
    if (w == 0) {
        a0 = (lane < 8) ? sh[lane]      : 0.f;
        a1 = (lane < 8) ? sh[8 + lane]  : 0.f;
        a2 = (lane < 8) ? sh[16 + lane] : 0.f;
        a0 = warpRed(a0); a1 = warpRed(a1); a2 = warpRed(a2);
        if (lane == 0) {
            // L2-direct stores (bypass L1); the release atomic below orders
            // them at gpu scope WITHOUT the CCTL.IVALL a __threadfence emits.
            __stcg(&g_psum[blk], a0);
            __stcg(&g_psq [blk], a1);
            __stcg(&g_pS  [blk], a2);
            unsigned int old;
            asm volatile("atom.global.acq_rel.gpu.add.u32 %0, [%1], %2;"
                         : "=r"(old)
                         : "l"(&g_ctr), "r"(1u)
                         : "memory");
            isLast = (old == NBLK - 1);
        }
    }
    __syncthreads();
    if (!isLast) return;

    // ---- Last block: combine 4096 partials -> scalar loss. ----
    // 8 warps; warp w reduces images 2w and 2w+1. All reads L1-bypass (fresh
    // from L2; producers' st.cg ordered by their release atomics).
    #pragma unroll
    for (int u = 0; u < 2; u++) {
        int img = (w << 1) | u;
        double ds = 0.0, dq = 0.0, dS = 0.0;
        #pragma unroll
        for (int j = lane; j < 64; j += 32) {
            float4 a = __ldcg((const float4*)&g_psum[img * 256 + j * 4]);
            float4 d = __ldcg((const float4*)&g_psq [img * 256 + j * 4]);
            float4 e = __ldcg((const float4*)&g_pS  [img * 256 + j * 4]);
            ds += ((double)a.x + (double)a.y) + ((double)a.z + (double)a.w);
            dq += ((double)d.x + (double)d.y) + ((double)d.z + (double)d.w);
            dS += ((double)e.x + (double)e.y) + ((double)e.z + (double)e.w);
        }
        ds = warpRedD(ds); dq = warpRedD(dq); dS = warpRedD(dS);
        if (lane == 0) {
            double n   = (double)HWn;
            double var = (dq - ds * ds / n) / (n - 1.0);
            shd[img] = (double)powf((float)var, 0.2f) * dS;
        }
    }
    __syncthreads();
    if (tid == 0) {
        double tot = 0.0;
        #pragma unroll
        for (int i = 0; i < 16; i++) tot += shd[i];
        out[0] = (float)(tot / (double)((long long)Bn * 3 * HWn));
        __stcg(&g_ctr, 0u);   // reset for the next graph replay
    }
}

extern "C" void kernel_launch(void* const* d_in, const int* in_sizes, int n_in,
                              void* d_out, int out_size) {
    const float* outp = (const float*)d_in[0];
    const float* emap = (const float*)d_in[1];
    const float* gtp  = (const float*)d_in[2];
    float* out = (float*)d_out;

    dim3 grid(Wn / TW, Hn / TH, Bn);
    k_fused<<<grid, 256>>>(outp, emap, gtp, out);
}

// round 12
// speedup vs baseline: 1.2835x; 1.2835x over previous
#include <cuda_runtime.h>
#include <math.h>

#define Bn    16
#define Hn    512
#define Wn    512
#define HWn   (Hn * Wn)

// tile: 64x16 outputs, halo 3 each side
#define TW    64
#define TH    16
#define EXTH  22          // TH + 6
#define SRS   72          // s_r cols: gc tx0-4 .. tx0+67
#define HSS   68          // h-sum stride

#define NBLK  4096        // 8 x 32 x 16 (image b owns slots [b*256, b*256+256))

__device__ float g_psum[NBLK], g_psq[NBLK], g_pS[NBLK];

__device__ __forceinline__ float warpRed(float v) {
    #pragma unroll
    for (int o = 16; o; o >>= 1) v += __shfl_down_sync(0xffffffffu, v, o);
    return v;
}
__device__ __forceinline__ int refl(int i) {
    i = (i < 0) ? -i : i;
    return (i >= Hn) ? (2 * (Hn - 1) - i) : i;
}

// ---------------------------------------------------------------------------
// ONE fused pass: residual + gate + per-image stats + separable 7x7 unbiased
// local variance (reflect pad) + gated loss partial. NO atomics, NO fences
// (any gpu-scope ordered op costs ~20us chip-wide via CCTL.IVALL — R10/R11).
// ---------------------------------------------------------------------------
__global__ __launch_bounds__(256, 6) void k_fused(const float* __restrict__ outp,
                                                  const float* __restrict__ emap,
                                                  const float* __restrict__ gtp) {
    __shared__ float  s_r [EXTH * SRS];   // rs (>=0) halo tile
    __shared__ float  s_hs[EXTH * HSS];   // horizontal 7-sum
    __shared__ float  s_hq[EXTH * HSS];   // horizontal 7-sum of squares
    __shared__ uchar4 s_g [256];          // gate bytes, 4 px each
    __shared__ float  sh  [24];

    int b   = blockIdx.z;
    int tx0 = blockIdx.x * TW;
    int ty0 = blockIdx.y * TH;
    int tid = threadIdx.x;
    int A0  = tx0 - 4;

    size_t bbase = (size_t)b * 3 * HWn;
    const float* gb = gtp  + bbase;
    const float* ob = outp + bbase;
    const float* eb = emap + bbase;

    // Phase 1: rs over halo tile, float4, row-reflect always (free).
    for (int i = tid; i < EXTH * 18; i += 256) {
        int row = i / 18, f4 = i - row * 18;
        int cb  = A0 + f4 * 4;
        if (cb >= 0 && cb <= Wn - 4) {
            int base = refl(ty0 + row - 3) * Wn + cb;
            float4 g0 = *(const float4*)(gb + base);
            float4 g1 = *(const float4*)(gb + base + HWn);
            float4 g2 = *(const float4*)(gb + base + 2 * HWn);
            float4 o0 = *(const float4*)(ob + base);
            float4 o1 = *(const float4*)(ob + base + HWn);
            float4 o2 = *(const float4*)(ob + base + 2 * HWn);
            float4 rs;
            rs.x = fabsf(g0.x-o0.x)+fabsf(g1.x-o1.x)+fabsf(g2.x-o2.x);
            rs.y = fabsf(g0.y-o0.y)+fabsf(g1.y-o1.y)+fabsf(g2.y-o2.y);
            rs.z = fabsf(g0.z-o0.z)+fabsf(g1.z-o1.z)+fabsf(g2.z-o2.z);
            rs.w = fabsf(g0.w-o0.w)+fabsf(g1.w-o1.w)+fabsf(g2.w-o2.w);
            *(float4*)&s_r[row * SRS + f4 * 4] = rs;
        }
    }
    __syncthreads();

    // Column-edge mirror fixup (left: gc -4..-1 ; right: gc 512..515).
    if (blockIdx.x == 0) {
        for (int i = tid; i < EXTH * 4; i += 256) {
            int row = i >> 2, k = i & 3;
            s_r[row * SRS + k] = s_r[row * SRS + 8 - k];
        }
    } else if (blockIdx.x == (Wn / TW) - 1) {
        for (int i = tid; i < EXTH * 4; i += 256) {
            int row = i >> 2, k = i & 3;
            s_r[row * SRS + 68 + k] = s_r[row * SRS + 66 - k];
        }
    }

    // Gate + per-image stats on center pixels (gt/out L1-hot, ema fresh).
    float lsum, lsq;
    {
        int r  = tid >> 4;
        int c4 = (tid & 15) * 4;
        int base = (ty0 + r) * Wn + tx0 + c4;
        float4 g0 = *(const float4*)(gb + base);
        float4 g1 = *(const float4*)(gb + base + HWn);
        float4 g2 = *(const float4*)(gb + base + 2 * HWn);
        float4 e0 = *(const float4*)(eb + base);
        float4 e1 = *(const float4*)(eb + base + HWn);
        float4 e2 = *(const float4*)(eb + base + 2 * HWn);
        float4 rs = *(const float4*)&s_r[(r + 3) * SRS + c4 + 4];
        float4 re;
        re.x = fabsf(g0.x-e0.x)+fabsf(g1.x-e1.x)+fabsf(g2.x-e2.x);
        re.y = fabsf(g0.y-e0.y)+fabsf(g1.y-e1.y)+fabsf(g2.y-e2.y);
        re.z = fabsf(g0.z-e0.z)+fabsf(g1.z-e1.z)+fabsf(g2.z-e2.z);
        re.w = fabsf(g0.w-e0.w)+fabsf(g1.w-e1.w)+fabsf(g2.w-e2.w);
        uchar4 gv;
        gv.x = (rs.x < re.x) ? 0 : 1;
        gv.y = (rs.y < re.y) ? 0 : 1;
        gv.z = (rs.z < re.z) ? 0 : 1;
        gv.w = (rs.w < re.w) ? 0 : 1;
        s_g[tid] = gv;
        lsum = rs.x + rs.y + rs.z + rs.w;
        lsq  = rs.x*rs.x + rs.y*rs.y + rs.z*rs.z + rs.w*rs.w;
    }
    __syncthreads();

    // Phase 2: horizontal 7-taps, 4 outputs/thread, sliding window.
    for (int i = tid; i < EXTH * 16; i += 256) {
        int row = i >> 4;
        int g4  = (i & 15) << 2;
        const float* rp = &s_r[row * SRS + g4];
        float4 A  = *(const float4*)(rp);
        float4 Bv = *(const float4*)(rp + 4);
        float4 Cv = *(const float4*)(rp + 8);
        float v0=A.y, v1=A.z, v2=A.w, v3=Bv.x, v4=Bv.y, v5=Bv.z, v6=Bv.w;
        float v7=Cv.x, v8=Cv.y, v9=Cv.z;
        float s0 = v0+v1+v2+v3+v4+v5+v6;
        float s1 = s0 - v0 + v7;
        float s2 = s1 - v1 + v8;
        float s3 = s2 - v2 + v9;
        float q0 = v0*v0+v1*v1+v2*v2+v3*v3+v4*v4+v5*v5+v6*v6;
        float q1 = q0 + (v7*v7 - v0*v0);
        float q2 = q1 + (v8*v8 - v1*v1);
        float q3 = q2 + (v9*v9 - v2*v2);
        *(float4*)&s_hs[row * HSS + g4] = make_float4(s0, s1, s2, s3);
        *(float4*)&s_hq[row * HSS + g4] = make_float4(q0, q1, q2, q3);
    }
    __syncthreads();

    // Phase 3: vertical 7-taps, register sliding window, 4 rows/thread.
    int c  = tid & 63;
    int r0 = (tid >> 6) * 4;
    float s = 0.f, q = 0.f;
    #pragma unroll
    for (int d = 0; d < 7; d++) {
        s += s_hs[(r0 + d) * HSS + c];
        q += s_hq[(r0 + d) * HSS + c];
    }
    float acc = 0.f;
    #pragma unroll
    for (int k = 0; k < 4; k++) {
        int r = r0 + k;
        float var = (q - s * s * (1.f / 49.f)) * (1.f / 48.f);
        float rs  = s_r[(r + 3) * SRS + c + 4];
        uchar4 gv = s_g[r * 16 + (c >> 2)];
        unsigned char gbit = (c & 2) ? ((c & 1) ? gv.w : gv.z)
                                     : ((c & 1) ? gv.y : gv.x);
        if (gbit) acc += fabsf(var) * rs;
        if (k < 3) {
            s += s_hs[(r + 7) * HSS + c] - s_hs[r * HSS + c];
            q += s_hq[(r + 7) * HSS + c] - s_hq[r * HSS + c];
        }
    }

    // Block reduce (lsum, lsq, acc) -> per-block partials. Plain stores.
    float a0 = warpRed(lsum), a1 = warpRed(lsq), a2 = warpRed(acc);
    int lane = tid & 31, w = tid >> 5;
    if (lane == 0) { sh[w] = a0; sh[8 + w] = a1; sh[16 + w] = a2; }
    __syncthreads();
    if (w == 0) {
        a0 = (lane < 8) ? sh[lane]      : 0.f;
        a1 = (lane < 8) ? sh[8 + lane]  : 0.f;
        a2 = (lane < 8) ? sh[16 + lane] : 0.f;
        a0 = warpRed(a0); a1 = warpRed(a1); a2 = warpRed(a2);
        if (lane == 0) {
            int blk = (blockIdx.z * 32 + blockIdx.y) * 8 + blockIdx.x;
            g_psum[blk] = a0; g_psq[blk] = a1; g_pS[blk] = a2;
        }
    }
}

// ---------------------------------------------------------------------------
// Final combine — FLOAT tree reductions (FP64 on one SM was the R9 15.5us
// bottleneck: ~12K DP ops @ ~18 cyc). Doubles only for 16 scalar variance
// computations (the one cancellation-sensitive step).
// ---------------------------------------------------------------------------
__global__ void k_final(float* __restrict__ out) {
    __shared__ double shd[16];
    int lane = threadIdx.x & 31, b = threadIdx.x >> 5;   // 512 threads, 16 warps
    float s = 0.f, q = 0.f, S = 0.f;
    #pragma unroll
    for (int j = 0; j < 8; j++) {
        int idx = b * 256 + j * 32 + lane;
        s += g_psum[idx];
        q += g_psq [idx];
        S += g_pS  [idx];
    }
    s = warpRed(s); q = warpRed(q); S = warpRed(S);
    if (lane == 0) {
        double n   = (double)HWn;
        double var = ((double)q - (double)s * (double)s / n) / (n - 1.0);
        shd[b] = (double)(powf((float)var, 0.2f) * S);
    }
    __syncthreads();
    if (threadIdx.x == 0) {
        double tot = 0.0;
        #pragma unroll
        for (int i = 0; i < 16; i++) tot += shd[i];
        out[0] = (float)(tot / (double)((long long)Bn * 3 * HWn));
    }
}

extern "C" void kernel_launch(void* const* d_in, const int* in_sizes, int n_in,
                              void* d_out, int out_size) {
    const float* outp = (const float*)d_in[0];
    const float* emap = (const float*)d_in[1];
    const float* gtp  = (const float*)d_in[2];
    float* out = (float*)d_out;

    dim3 grid(Wn / TW, Hn / TH, Bn);
    k_fused<<<grid, 256>>>(outp, emap, gtp);
    k_final<<<1, 512>>>(out);
}

// round 13
// speedup vs baseline: 1.3516x; 1.0530x over previous
#include <cuda_runtime.h>
#include <math.h>

#define Bn    16
#define Hn    512
#define Wn    512
#define HWn   (Hn * Wn)

// tile: 64x16 outputs, halo 3 each side
#define TW    64
#define TH    16
#define EXTH  22          // TH + 6
#define SRS   72          // s_r cols: gc tx0-4 .. tx0+67
#define HSS   68          // h-sum stride

#define NBLK  4096        // 8 x 32 x 16 (image b owns slots [b*256, b*256+256))

__device__ float g_psum[NBLK], g_psq[NBLK], g_pS[NBLK];

__device__ __forceinline__ float warpRed(float v) {
    #pragma unroll
    for (int o = 16; o; o >>= 1) v += __shfl_down_sync(0xffffffffu, v, o);
    return v;
}
__device__ __forceinline__ int refl(int i) {
    i = (i < 0) ? -i : i;
    return (i >= Hn) ? (2 * (Hn - 1) - i) : i;
}

// ---------------------------------------------------------------------------
// ONE fused pass: residual + gate + per-image stats + separable 7x7 unbiased
// local variance (reflect pad) + gated loss partial. NO atomics, NO fences
// (any gpu-scope ordered op costs ~20us chip-wide via CCTL.IVALL — R10/R11).
// ---------------------------------------------------------------------------
__global__ __launch_bounds__(256, 8) void k_fused(const float* __restrict__ outp,
                                                  const float* __restrict__ emap,
                                                  const float* __restrict__ gtp) {
    __shared__ float  s_r [EXTH * SRS];   // rs (>=0) halo tile
    __shared__ float  s_hs[EXTH * HSS];   // horizontal 7-sum
    __shared__ float  s_hq[EXTH * HSS];   // horizontal 7-sum of squares
    __shared__ uchar4 s_g [256];          // gate bytes, 4 px each
    __shared__ float  sh  [24];

    int b   = blockIdx.z;
    int tx0 = blockIdx.x * TW;
    int ty0 = blockIdx.y * TH;
    int tid = threadIdx.x;
    int A0  = tx0 - 4;

    size_t bbase = (size_t)b * 3 * HWn;
    const float* gb = gtp  + bbase;
    const float* ob = outp + bbase;
    const float* eb = emap + bbase;

    // Phase 1: rs over halo tile, float4, row-reflect always (free).
    for (int i = tid; i < EXTH * 18; i += 256) {
        int row = i / 18, f4 = i - row * 18;
        int cb  = A0 + f4 * 4;
        if (cb >= 0 && cb <= Wn - 4) {
            int base = refl(ty0 + row - 3) * Wn + cb;
            float4 g0 = *(const float4*)(gb + base);
            float4 g1 = *(const float4*)(gb + base + HWn);
            float4 g2 = *(const float4*)(gb + base + 2 * HWn);
            float4 o0 = *(const float4*)(ob + base);
            float4 o1 = *(const float4*)(ob + base + HWn);
            float4 o2 = *(const float4*)(ob + base + 2 * HWn);
            float4 rs;
            rs.x = fabsf(g0.x-o0.x)+fabsf(g1.x-o1.x)+fabsf(g2.x-o2.x);
            rs.y = fabsf(g0.y-o0.y)+fabsf(g1.y-o1.y)+fabsf(g2.y-o2.y);
            rs.z = fabsf(g0.z-o0.z)+fabsf(g1.z-o1.z)+fabsf(g2.z-o2.z);
            rs.w = fabsf(g0.w-o0.w)+fabsf(g1.w-o1.w)+fabsf(g2.w-o2.w);
            *(float4*)&s_r[row * SRS + f4 * 4] = rs;
        }
    }
    __syncthreads();

    // Column-edge mirror fixup (left: gc -4..-1 ; right: gc 512..515).
    if (blockIdx.x == 0) {
        for (int i = tid; i < EXTH * 4; i += 256) {
            int row = i >> 2, k = i & 3;
            s_r[row * SRS + k] = s_r[row * SRS + 8 - k];
        }
    } else if (blockIdx.x == (Wn / TW) - 1) {
        for (int i = tid; i < EXTH * 4; i += 256) {
            int row = i >> 2, k = i & 3;
            s_r[row * SRS + 68 + k] = s_r[row * SRS + 66 - k];
        }
    }

    // Gate + per-image stats on center pixels (gt/out L1-hot, ema fresh).
    float lsum, lsq;
    {
        int r  = tid >> 4;
        int c4 = (tid & 15) * 4;
        int base = (ty0 + r) * Wn + tx0 + c4;
        float4 g0 = *(const float4*)(gb + base);
        float4 g1 = *(const float4*)(gb + base + HWn);
        float4 g2 = *(const float4*)(gb + base + 2 * HWn);
        float4 e0 = *(const float4*)(eb + base);
        float4 e1 = *(const float4*)(eb + base + HWn);
        float4 e2 = *(const float4*)(eb + base + 2 * HWn);
        float4 rs = *(const float4*)&s_r[(r + 3) * SRS + c4 + 4];
        float4 re;
        re.x = fabsf(g0.x-e0.x)+fabsf(g1.x-e1.x)+fabsf(g2.x-e2.x);
        re.y = fabsf(g0.y-e0.y)+fabsf(g1.y-e1.y)+fabsf(g2.y-e2.y);
        re.z = fabsf(g0.z-e0.z)+fabsf(g1.z-e1.z)+fabsf(g2.z-e2.z);
        re.w = fabsf(g0.w-e0.w)+fabsf(g1.w-e1.w)+fabsf(g2.w-e2.w);
        uchar4 gv;
        gv.x = (rs.x < re.x) ? 0 : 1;
        gv.y = (rs.y < re.y) ? 0 : 1;
        gv.z = (rs.z < re.z) ? 0 : 1;
        gv.w = (rs.w < re.w) ? 0 : 1;
        s_g[tid] = gv;
        lsum = rs.x + rs.y + rs.z + rs.w;
        lsq  = rs.x*rs.x + rs.y*rs.y + rs.z*rs.z + rs.w*rs.w;
    }
    __syncthreads();

    // Phase 2: horizontal 7-taps, 4 outputs/thread, sliding window.
    for (int i = tid; i < EXTH * 16; i += 256) {
        int row = i >> 4;
        int g4  = (i & 15) << 2;
        const float* rp = &s_r[row * SRS + g4];
        float4 A  = *(const float4*)(rp);
        float4 Bv = *(const float4*)(rp + 4);
        float4 Cv = *(const float4*)(rp + 8);
        float v0=A.y, v1=A.z, v2=A.w, v3=Bv.x, v4=Bv.y, v5=Bv.z, v6=Bv.w;
        float v7=Cv.x, v8=Cv.y, v9=Cv.z;
        float s0 = v0+v1+v2+v3+v4+v5+v6;
        float s1 = s0 - v0 + v7;
        float s2 = s1 - v1 + v8;
        float s3 = s2 - v2 + v9;
        float q0 = v0*v0+v1*v1+v2*v2+v3*v3+v4*v4+v5*v5+v6*v6;
        float q1 = q0 + (v7*v7 - v0*v0);
        float q2 = q1 + (v8*v8 - v1*v1);
        float q3 = q2 + (v9*v9 - v2*v2);
        *(float4*)&s_hs[row * HSS + g4] = make_float4(s0, s1, s2, s3);
        *(float4*)&s_hq[row * HSS + g4] = make_float4(q0, q1, q2, q3);
    }
    __syncthreads();

    // Phase 3: vertical 7-taps, register sliding window, 4 rows/thread.
    int c  = tid & 63;
    int r0 = (tid >> 6) * 4;
    float s = 0.f, q = 0.f;
    #pragma unroll
    for (int d = 0; d < 7; d++) {
        s += s_hs[(r0 + d) * HSS + c];
        q += s_hq[(r0 + d) * HSS + c];
    }
    float acc = 0.f;
    #pragma unroll
    for (int k = 0; k < 4; k++) {
        int r = r0 + k;
        float var = (q - s * s * (1.f / 49.f)) * (1.f / 48.f);
        float rs  = s_r[(r + 3) * SRS + c + 4];
        uchar4 gv = s_g[r * 16 + (c >> 2)];
        unsigned char gbit = (c & 2) ? ((c & 1) ? gv.w : gv.z)
                                     : ((c & 1) ? gv.y : gv.x);
        if (gbit) acc += fabsf(var) * rs;
        if (k < 3) {
            s += s_hs[(r + 7) * HSS + c] - s_hs[r * HSS + c];
            q += s_hq[(r + 7) * HSS + c] - s_hq[r * HSS + c];
        }
    }

    // Block reduce (lsum, lsq, acc) -> per-block partials. Plain stores.
    float a0 = warpRed(lsum), a1 = warpRed(lsq), a2 = warpRed(acc);
    int lane = tid & 31, w = tid >> 5;
    if (lane == 0) { sh[w] = a0; sh[8 + w] = a1; sh[16 + w] = a2; }
    __syncthreads();
    if (w == 0) {
        a0 = (lane < 8) ? sh[lane]      : 0.f;
        a1 = (lane < 8) ? sh[8 + lane]  : 0.f;
        a2 = (lane < 8) ? sh[16 + lane] : 0.f;
        a0 = warpRed(a0); a1 = warpRed(a1); a2 = warpRed(a2);
        if (lane == 0) {
            int blk = (blockIdx.z * 32 + blockIdx.y) * 8 + blockIdx.x;
            g_psum[blk] = a0; g_psq[blk] = a1; g_pS[blk] = a2;
        }
    }
}

// ---------------------------------------------------------------------------
// Final combine — float tree reductions, 32 warps (2 per image), PDL-launched
// so its setup overlaps k_fused's tail. Doubles only for the 16 variance
// scalars (cancellation-sensitive).
// ---------------------------------------------------------------------------
__global__ void k_final(float* __restrict__ out) {
#if __CUDA_ARCH__ >= 900
    cudaGridDependencySynchronize();   // PDL: wait for k_fused's memory
#endif
    __shared__ float sh_s[32], sh_q[32], sh_S[32];
    int lane = threadIdx.x & 31, w = threadIdx.x >> 5;   // 1024 thr, 32 warps
    int img  = w >> 1;
    int base = img * 256 + (w & 1) * 128;
    float s = 0.f, q = 0.f, S = 0.f;
    #pragma unroll
    for (int j = 0; j < 4; j++) {
        int idx = base + j * 32 + lane;
        s += g_psum[idx];
        q += g_psq [idx];
        S += g_pS  [idx];
    }
    s = warpRed(s); q = warpRed(q); S = warpRed(S);
    if (lane == 0) { sh_s[w] = s; sh_q[w] = q; sh_S[w] = S; }
    __syncthreads();
    if (w == 0) {
        double contrib = 0.0;
        if (lane < 16) {
            float s2 = sh_s[2*lane] + sh_s[2*lane + 1];
            float q2 = sh_q[2*lane] + sh_q[2*lane + 1];
            float S2 = sh_S[2*lane] + sh_S[2*lane + 1];
            double n   = (double)HWn;
            double var = ((double)q2 - (double)s2 * (double)s2 / n) / (n - 1.0);
            contrib = (double)(powf((float)var, 0.2f) * S2);
        }
        #pragma unroll
        for (int o = 16; o; o >>= 1)
            contrib += __shfl_down_sync(0xffffffffu, contrib, o);
        if (lane == 0)
            out[0] = (float)(contrib / (double)((long long)Bn * 3 * HWn));
    }
}

extern "C" void kernel_launch(void* const* d_in, const int* in_sizes, int n_in,
                              void* d_out, int out_size) {
    const float* outp = (const float*)d_in[0];
    const float* emap = (const float*)d_in[1];
    const float* gtp  = (const float*)d_in[2];
    float* out = (float*)d_out;

    dim3 grid(Wn / TW, Hn / TH, Bn);
    k_fused<<<grid, 256>>>(outp, emap, gtp);

    // PDL launch: k_final's setup overlaps k_fused's tail; the device-side
    // cudaGridDependencySynchronize provides the ordering.
    cudaLaunchConfig_t cfg = {};
    cfg.gridDim  = dim3(1, 1, 1);
    cfg.blockDim = dim3(1024, 1, 1);
    cfg.dynamicSmemBytes = 0;
    cfg.stream = 0;
    cudaLaunchAttribute attrs[1];
    attrs[0].id = cudaLaunchAttributeProgrammaticStreamSerialization;
    attrs[0].val.programmaticStreamSerializationAllowed = 1;
    cfg.attrs = attrs;
    cfg.numAttrs = 1;
    cudaError_t e = cudaLaunchKernelEx(&cfg, k_final, out);
    if (e != cudaSuccess) {
        // Fallback: plain launch (still correct, just no overlap).
        k_final<<<1, 1024>>>(out);
    }
}